// round 14
// baseline (speedup 1.0000x reference)
#include <cuda_runtime.h>
#include <cuda_bf16.h>
#include <cstdint>

#define BSZ 16
#define DV  448
#define DP  512
#define HW  4096
typedef __nv_bfloat16 bf16;
typedef uint32_t u32;

#define TB32 8192                // one 128x32 bf16 tile
#define STG (4*TB32)             // Ah | Al | Bh | Bl = 32 KB
#define SM_GEMM (3*STG + 128)    // 3 stages + mbarriers -> 2 CTAs/SM
#define STG1 (2*TB32)            // A | B = 16 KB (1-term path)
#define SM_G1 (3*STG1 + 128)     // 48 KB

// ---------------- scratch (zero-init; pad regions never written -> stay 0) ----------------
__device__ bf16 g_Wh[(size_t)3*DP*DV],  g_Wl[(size_t)3*DP*DV];
__device__ bf16 g_Yrh[(size_t)BSZ*DP*HW], g_Yrl[(size_t)BSZ*DP*HW];   // Vr split [b][c][h]
__device__ bf16 g_Ysh[(size_t)BSZ*DP*HW], g_Ysl[(size_t)BSZ*DP*HW];   // Vs split [b][c][h]
__device__ bf16 g_Xrh[(size_t)BSZ*HW*DV], g_Xrl[(size_t)BSZ*HW*DV];   // Vr^T split [b][h][c]
__device__ bf16 g_Mh[(size_t)BSZ*2*DP*DP], g_Ml[(size_t)BSZ*DP*DP];   // M' (neg half: hi only)
__device__ bf16 g_Th[(size_t)BSZ*2*DP*DP], g_Tl[(size_t)BSZ*DP*DP];   // T  (neg half: hi only)
__device__ bf16 g_Vthi[(size_t)BSZ*HW*DP], g_Vtlo[(size_t)BSZ*HW*DP]; // V^T = (Wv·Vr)^T
__device__ float g_S [(size_t)BSZ*DP*DP];
__device__ float g_Sn[(size_t)BSZ*DP*DP];
__device__ bf16 g_Aphi[(size_t)BSZ*DP*DP], g_Aplo[(size_t)BSZ*DP*DP];
__device__ bf16 g_Anhi[(size_t)BSZ*DP*DP];
__device__ double g_Ltr;

// ---------------- helpers ----------------
__device__ __forceinline__ u32 smem_u32(const void* p) {
    u32 a;
    asm("{ .reg .u64 t; cvta.to.shared.u64 t, %1; cvt.u32.u64 %0, t; }" : "=r"(a) : "l"(p));
    return a;
}
__device__ __forceinline__ u32 off32(int r, int c) {
    return (u32)(r * 64 + ((c ^ ((r >> 1) & 3)) << 4));
}
__device__ __forceinline__ void ldsm4(u32* r, u32 addr) {
    asm volatile("ldmatrix.sync.aligned.m8n8.x4.shared.b16 {%0,%1,%2,%3}, [%4];"
                 : "=r"(r[0]), "=r"(r[1]), "=r"(r[2]), "=r"(r[3]) : "r"(addr));
}
__device__ __forceinline__ void mma16816(float* c, const u32* a, u32 b0, u32 b1) {
    asm volatile("mma.sync.aligned.m16n8k16.row.col.f32.bf16.bf16.f32 "
                 "{%0,%1,%2,%3}, {%4,%5,%6,%7}, {%8,%9}, {%0,%1,%2,%3};"
                 : "+f"(c[0]), "+f"(c[1]), "+f"(c[2]), "+f"(c[3])
                 : "r"(a[0]), "r"(a[1]), "r"(a[2]), "r"(a[3]), "r"(b0), "r"(b1));
}
__device__ __forceinline__ void cpasync16(u32 sa, const void* g) {
    asm volatile("cp.async.cg.shared.global [%0], [%1], 16;" :: "r"(sa), "l"(g));
}
__device__ __forceinline__ void minit(u32 mb, u32 cnt) {
    asm volatile("mbarrier.init.shared.b64 [%0], %1;" :: "r"(mb), "r"(cnt) : "memory");
}
__device__ __forceinline__ void marrive(u32 mb) {
    asm volatile("mbarrier.arrive.shared.b64 _, [%0];" :: "r"(mb) : "memory");
}
__device__ __forceinline__ void cp_arrive(u32 mb) {
    asm volatile("cp.async.mbarrier.arrive.noinc.shared.b64 [%0];" :: "r"(mb) : "memory");
}
__device__ __forceinline__ void mwait(u32 mb, u32 ph) {
    asm volatile(
        "{\n\t.reg .pred P;\n\tWL%=:\n\t"
        "mbarrier.try_wait.parity.acquire.cta.shared::cta.b64 P, [%0], %1, 0x989680;\n\t"
        "@P bra WD%=;\n\tbra WL%=;\n\tWD%=:\n\t}" :: "r"(mb), "r"(ph) : "memory");
}

__device__ __forceinline__ void split2(float x0, float x1, u32& hw_, u32& lw) {
    bf16 h0 = __float2bfloat16(x0), h1 = __float2bfloat16(x1);
    bf16 l0 = __float2bfloat16(x0 - __bfloat162float(h0));
    bf16 l1 = __float2bfloat16(x1 - __bfloat162float(h1));
    hw_ = (u32)(*(uint16_t*)&h0) | ((u32)(*(uint16_t*)&h1) << 16);
    lw  = (u32)(*(uint16_t*)&l0) | ((u32)(*(uint16_t*)&l1) << 16);
}
__device__ __forceinline__ u32 pack2(float x0, float x1) {
    bf16 h0 = __float2bfloat16(x0), h1 = __float2bfloat16(x1);
    return (u32)(*(uint16_t*)&h0) | ((u32)(*(uint16_t*)&h1) << 16);
}
__device__ __forceinline__ void split8(const float* x, uint4& hi, uint4& lo) {
    u32 h[4], l[4];
#pragma unroll
    for (int j = 0; j < 4; j++) split2(x[2*j], x[2*j+1], h[j], l[j]);
    hi = make_uint4(h[0], h[1], h[2], h[3]);
    lo = make_uint4(l[0], l[1], l[2], l[3]);
}

// ---------------- producer: one 128x32 tile, 256 threads ----------------
__device__ __forceinline__ void issueT(u32 sbase, const bf16* __restrict__ g, int ld,
                                       int k0, int tid) {
#pragma unroll
    for (int i = 0; i < 2; i++) {
        int task = i * 256 + tid, r = task >> 2, c = task & 3;
        cpasync16(sbase + off32(r, c), g + (size_t)r * ld + k0 + c * 8);
    }
}
__device__ __forceinline__ void issue_stage(u32 base,
        const bf16* Ah, const bf16* Al, int lda,
        const bf16* Bh, const bf16* Bl, int ldb, int k0, int tid) {
    issueT(base,          Ah, lda, k0, tid);
    issueT(base + TB32,   Al, lda, k0, tid);
    issueT(base + 2*TB32, Bh, ldb, k0, tid);
    issueT(base + 3*TB32, Bl, ldb, k0, tid);
}

// ---------------- 3-term fragment load + mma ----------------
__device__ __forceinline__ void ld_frags(u32 base, int ks, int lane, int wm, int wn,
        u32 ah[4][4], u32 al[4][4], u32 bh[2][4], u32 bl[2][4]) {
    int lm = lane & 15, lk = lane >> 4;
    int ch = ks * 2 + lk;
#pragma unroll
    for (int mt = 0; mt < 4; mt++) {
        int r = wm * 64 + mt * 16 + lm;
        ldsm4(ah[mt], base +        off32(r, ch));
        ldsm4(al[mt], base + TB32 + off32(r, ch));
    }
#pragma unroll
    for (int nt = 0; nt < 2; nt++) {
        int r = wn * 32 + nt * 16 + lm;
        ldsm4(bh[nt], base + 2*TB32 + off32(r, ch));
        ldsm4(bl[nt], base + 3*TB32 + off32(r, ch));
    }
}
__device__ __forceinline__ void mma_frags(float acc[4][4][4],
        u32 ah[4][4], u32 al[4][4], u32 bh[2][4], u32 bl[2][4]) {
#pragma unroll
    for (int mt = 0; mt < 4; mt++)
#pragma unroll
        for (int nt = 0; nt < 4; nt++)
            mma16816(acc[mt][nt], ah[mt], bh[nt>>1][nt&1], bh[nt>>1][(nt&1)+2]);
#pragma unroll
    for (int mt = 0; mt < 4; mt++)
#pragma unroll
        for (int nt = 0; nt < 4; nt++)
            mma16816(acc[mt][nt], ah[mt], bl[nt>>1][nt&1], bl[nt>>1][(nt&1)+2]);
#pragma unroll
    for (int mt = 0; mt < 4; mt++)
#pragma unroll
        for (int nt = 0; nt < 4; nt++)
            mma16816(acc[mt][nt], al[mt], bh[nt>>1][nt&1], bh[nt>>1][(nt&1)+2]);
}

// ---------------- 3-term mbarrier-pipelined mainloop (CTA 128x128, k-tile 32) ----------
__device__ __forceinline__ void gemm_main(u32 sb, u32 mb, float acc[4][4][4],
        const bf16* Ah, const bf16* Al, int lda,
        const bf16* Bh, const bf16* Bl, int ldb,
        int NT, int tid, int lane, int wm, int wn) {
    if (tid == 0)
#pragma unroll
        for (int s = 0; s < 3; s++) { minit(mb + s*8, 256); minit(mb + 24 + s*8, 8); }
    __syncthreads();
#pragma unroll 1
    for (int s = 0; s < 2; s++) {
        issue_stage(sb + s * STG, Ah, Al, lda, Bh, Bl, ldb, s * 32, tid);
        cp_arrive(mb + s*8);
    }
#pragma unroll 1
    for (int it = 0; it < NT; it++) {
        int s = it % 3;
        mwait(mb + s*8, (it / 3) & 1);
        u32 base = sb + s * STG;
        u32 ah[4][4], al[4][4], bh[2][4], bl[2][4];
        ld_frags(base, 0, lane, wm, wn, ah, al, bh, bl);
        if (it + 2 < NT) {
            int pi = it + 2, ps = pi % 3;
            mwait(mb + 24 + ps*8, 1u ^ ((u32)(pi / 3) & 1));
            issue_stage(sb + ps * STG, Ah, Al, lda, Bh, Bl, ldb, pi * 32, tid);
            cp_arrive(mb + ps*8);
        }
        mma_frags(acc, ah, al, bh, bl);
        ld_frags(base, 1, lane, wm, wn, ah, al, bh, bl);
        if (lane == 0) marrive(mb + 24 + s*8);
        mma_frags(acc, ah, al, bh, bl);
    }
}

// ---------------- 1-term mainloop (plain bf16, CTA 128x128, k-tile 32) ----------------
__device__ __forceinline__ void gemm_one(u32 sb, u32 mb, float acc[4][4][4],
        const bf16* A, int lda, const bf16* B, int ldb,
        int NT, int tid, int lane, int wm, int wn) {
    if (tid == 0)
#pragma unroll
        for (int s = 0; s < 3; s++) { minit(mb + s*8, 256); minit(mb + 24 + s*8, 8); }
    __syncthreads();
#pragma unroll 1
    for (int s = 0; s < 2; s++) {
        issueT(sb + s * STG1,        A, lda, s * 32, tid);
        issueT(sb + s * STG1 + TB32, B, ldb, s * 32, tid);
        cp_arrive(mb + s*8);
    }
    int lm = lane & 15, lk = lane >> 4;
#pragma unroll 1
    for (int it = 0; it < NT; it++) {
        int s = it % 3;
        mwait(mb + s*8, (it / 3) & 1);
        u32 base = sb + s * STG1;
#pragma unroll
        for (int ks = 0; ks < 2; ks++) {
            int ch = ks * 2 + lk;
            u32 ah[4][4], bh[2][4];
#pragma unroll
            for (int mt = 0; mt < 4; mt++) {
                int r = wm * 64 + mt * 16 + lm;
                ldsm4(ah[mt], base + off32(r, ch));
            }
#pragma unroll
            for (int nt = 0; nt < 2; nt++) {
                int r = wn * 32 + nt * 16 + lm;
                ldsm4(bh[nt], base + TB32 + off32(r, ch));
            }
            if (ks == 0 && it + 2 < NT) {
                int pi = it + 2, ps = pi % 3;
                mwait(mb + 24 + ps*8, 1u ^ ((u32)(pi / 3) & 1));
                issueT(sb + ps * STG1,        A, lda, pi * 32, tid);
                issueT(sb + ps * STG1 + TB32, B, ldb, pi * 32, tid);
                cp_arrive(mb + ps*8);
            }
            if (ks == 1 && lane == 0) marrive(mb + 24 + s*8);
#pragma unroll
            for (int mt = 0; mt < 4; mt++)
#pragma unroll
                for (int nt = 0; nt < 4; nt++)
                    mma16816(acc[mt][nt], ah[mt], bh[nt>>1][nt&1], bh[nt>>1][(nt&1)+2]);
        }
    }
}

// ---------------- epilogues ----------------
__device__ __forceinline__ void store_split(bf16* Dh, bf16* Dl, size_t base, int ldc,
        float acc[4][4][4], int m0, int n0, int lane, int wm, int wn) {
#pragma unroll
    for (int mt = 0; mt < 4; mt++)
#pragma unroll
        for (int nt = 0; nt < 4; nt++)
#pragma unroll
            for (int h = 0; h < 2; h++) {
                int r = m0 + wm * 64 + mt * 16 + (lane >> 2) + h * 8;
                int c = n0 + wn * 32 + nt * 8 + (lane & 3) * 2;
                u32 hw_, lw;
                split2(acc[mt][nt][h*2], acc[mt][nt][h*2+1], hw_, lw);
                *(u32*)(Dh + base + (size_t)r * ldc + c) = hw_;
                *(u32*)(Dl + base + (size_t)r * ldc + c) = lw;
            }
}
__device__ __forceinline__ void store_hi(bf16* Dh, size_t base, int ldc,
        float acc[4][4][4], int m0, int n0, int lane, int wm, int wn) {
#pragma unroll
    for (int mt = 0; mt < 4; mt++)
#pragma unroll
        for (int nt = 0; nt < 4; nt++)
#pragma unroll
            for (int h = 0; h < 2; h++) {
                int r = m0 + wm * 64 + mt * 16 + (lane >> 2) + h * 8;
                int c = n0 + wn * 32 + nt * 8 + (lane & 3) * 2;
                *(u32*)(Dh + base + (size_t)r * ldc + c) =
                    pack2(acc[mt][nt][h*2], acc[mt][nt][h*2+1]);
            }
}

// ---------------- pre-passes ----------------
__global__ void convw_kernel(const float* __restrict__ Wq, const float* __restrict__ Wk,
                             const float* __restrict__ Wv) {
    int t = blockIdx.x * 256 + threadIdx.x;
    const int half = DV * DV / 2;
    if (t >= 3 * half) return;
    int p = t / half, rem = t - p * half;
    int m = rem / (DV / 2), kp = rem - m * (DV / 2);
    const float* W = (p == 0) ? Wq : (p == 1) ? Wk : Wv;
    u32 hw_, lw;
    split2(W[m * DV + kp * 2], W[m * DV + kp * 2 + 1], hw_, lw);
    size_t g = ((size_t)p * DP + m) * DV + kp * 2;
    *(u32*)(g_Wh + g) = hw_;
    *(u32*)(g_Wl + g) = lw;
}

__global__ void convy_kernel(const float* __restrict__ Vr, const float* __restrict__ Vs) {
    int z = blockIdx.z, b = z >> 1, which = z & 1;
    const float* V = (which ? Vr : Vs) + (size_t)b * DV * HW;
    bf16* Yh = which ? g_Yrh : g_Ysh;
    bf16* Yl = which ? g_Yrl : g_Ysl;
    int c = blockIdx.y;
    int h = blockIdx.x * 512 + threadIdx.x * 2;
    float2 v = *(const float2*)(V + (size_t)c * HW + h);
    u32 hw_, lw;
    split2(v.x, v.y, hw_, lw);
    size_t g = ((size_t)b * DP + c) * HW + h;
    *(u32*)(Yh + g) = hw_;
    *(u32*)(Yl + g) = lw;
}

__global__ void convx_kernel(const float* __restrict__ Vr) {
    __shared__ float tile[32][33];
    int b = blockIdx.z;
    const float* V = Vr + (size_t)b * DV * HW;
    int h0 = blockIdx.x * 32, c0 = blockIdx.y * 32;
    int t = threadIdx.x, tx = t & 31, ty = t >> 5;
#pragma unroll
    for (int j = 0; j < 4; j++) {
        int cc = ty * 4 + j;
        tile[cc][tx] = V[(size_t)(c0 + cc) * HW + h0 + tx];
    }
    __syncthreads();
#pragma unroll
    for (int i = 0; i < 2; i++) {
        int task = i * 256 + t, hh = task >> 4, cp = task & 15;
        u32 hw_, lw;
        split2(tile[cp*2][hh], tile[cp*2+1][hh], hw_, lw);
        size_t g = ((size_t)b * HW + h0 + hh) * DV + c0 + cp * 2;
        *(u32*)(g_Xrh + g) = hw_;
        *(u32*)(g_Xrl + g) = lw;
    }
}

// ---------------- K1a: M'pos = Vr[b] · Vs[b]^T (3-term, K=4096) ----------------
__global__ void __launch_bounds__(256, 2)
mmp_kernel() {
    extern __shared__ char smem[];
    u32 sb = smem_u32(smem), mb = sb + 3*STG;
    int tid = threadIdx.x, lane = tid & 31, wid = tid >> 5, wm = wid & 1, wn = wid >> 1;
    int b = blockIdx.z;
    int m0 = blockIdx.y * 128, n0 = blockIdx.x * 128;
    float acc[4][4][4] = {};
    gemm_main(sb, mb, acc,
              g_Yrh + ((size_t)b * DP + m0) * HW, g_Yrl + ((size_t)b * DP + m0) * HW, HW,
              g_Ysh + ((size_t)b * DP + n0) * HW, g_Ysl + ((size_t)b * DP + n0) * HW, HW,
              HW / 32, tid, lane, wm, wn);
    store_split(g_Mh, g_Ml, (size_t)b * DP * DP, DP, acc, m0, n0, lane, wm, wn);
}

// ---------------- K1b: M'neg = Vr[b+1] · Vs[b]^T (1-term bf16) ----------------
__global__ void __launch_bounds__(256, 2)
mmn_kernel() {
    extern __shared__ char smem[];
    u32 sb = smem_u32(smem), mb = sb + 3*STG1;
    int tid = threadIdx.x, lane = tid & 31, wid = tid >> 5, wm = wid & 1, wn = wid >> 1;
    int b = blockIdx.z, bk = (b + 1) & (BSZ - 1);
    int m0 = blockIdx.y * 128, n0 = blockIdx.x * 128;
    float acc[4][4][4] = {};
    gemm_one(sb, mb, acc,
             g_Yrh + ((size_t)bk * DP + m0) * HW, HW,
             g_Ysh + ((size_t)b  * DP + n0) * HW, HW,
             HW / 32, tid, lane, wm, wn);
    store_hi(g_Mh, (size_t)(BSZ + b) * DP * DP, DP, acc, m0, n0, lane, wm, wn);
}

// ---------------- K2a: Tpos = Wq @ M'pos^T (3-term, K=448) ----------------
__global__ void __launch_bounds__(256, 2)
tp_kernel() {
    extern __shared__ char smem[];
    u32 sb = smem_u32(smem), mb = sb + 3*STG;
    int tid = threadIdx.x, lane = tid & 31, wid = tid >> 5, wm = wid & 1, wn = wid >> 1;
    int b = blockIdx.z;
    int m0 = blockIdx.y * 128, n0 = blockIdx.x * 128;
    float acc[4][4][4] = {};
    gemm_main(sb, mb, acc,
              g_Wh + (size_t)m0 * DV, g_Wl + (size_t)m0 * DV, DV,
              g_Mh + (size_t)b * DP * DP + (size_t)n0 * DP,
              g_Ml + (size_t)b * DP * DP + (size_t)n0 * DP, DP,
              DV / 32, tid, lane, wm, wn);
    store_split(g_Th, g_Tl, (size_t)b * DP * DP, DP, acc, m0, n0, lane, wm, wn);
}

// ---------------- K2b: Tneg = Wq @ M'neg^T (1-term) ----------------
__global__ void __launch_bounds__(256, 2)
tn_kernel() {
    extern __shared__ char smem[];
    u32 sb = smem_u32(smem), mb = sb + 3*STG1;
    int tid = threadIdx.x, lane = tid & 31, wid = tid >> 5, wm = wid & 1, wn = wid >> 1;
    int b = blockIdx.z;
    int m0 = blockIdx.y * 128, n0 = blockIdx.x * 128;
    float acc[4][4][4] = {};
    gemm_one(sb, mb, acc,
             g_Wh + (size_t)m0 * DV, DV,
             g_Mh + (size_t)(BSZ + b) * DP * DP + (size_t)n0 * DP, DP,
             DV / 32, tid, lane, wm, wn);
    store_hi(g_Th, (size_t)(BSZ + b) * DP * DP, DP, acc, m0, n0, lane, wm, wn);
}

// ---------------- K3a: Spos = Tpos @ Wk^T (3-term, K=448) ----------------
__global__ void __launch_bounds__(256, 2)
sp_kernel() {
    extern __shared__ char smem[];
    u32 sb = smem_u32(smem), mb = sb + 3*STG;
    int tid = threadIdx.x, lane = tid & 31, wid = tid >> 5, wm = wid & 1, wn = wid >> 1;
    int b = blockIdx.z;
    int m0 = blockIdx.y * 128, n0 = blockIdx.x * 128;
    float acc[4][4][4] = {};
    gemm_main(sb, mb, acc,
              g_Th + (size_t)b * DP * DP + (size_t)m0 * DP,
              g_Tl + (size_t)b * DP * DP + (size_t)m0 * DP, DP,
              g_Wh + ((size_t)DP + n0) * DV, g_Wl + ((size_t)DP + n0) * DV, DV,
              DV / 32, tid, lane, wm, wn);
    float* C = g_S + (size_t)b * DP * DP;
#pragma unroll
    for (int mt = 0; mt < 4; mt++)
#pragma unroll
        for (int nt = 0; nt < 4; nt++)
#pragma unroll
            for (int h = 0; h < 2; h++) {
                int r = m0 + wm * 64 + mt * 16 + (lane >> 2) + h * 8;
                int c = n0 + wn * 32 + nt * 8 + (lane & 3) * 2;
                float2 v = {acc[mt][nt][h*2], acc[mt][nt][h*2+1]};
                *(float2*)(C + (size_t)r * DP + c) = v;
            }
}

// ---------------- K3b: Sneg = Tneg @ Wk^T (1-term) ----------------
__global__ void __launch_bounds__(256, 2)
sn_kernel() {
    extern __shared__ char smem[];
    u32 sb = smem_u32(smem), mb = sb + 3*STG1;
    int tid = threadIdx.x, lane = tid & 31, wid = tid >> 5, wm = wid & 1, wn = wid >> 1;
    int b = blockIdx.z;
    int m0 = blockIdx.y * 128, n0 = blockIdx.x * 128;
    float acc[4][4][4] = {};
    gemm_one(sb, mb, acc,
             g_Th + (size_t)(BSZ + b) * DP * DP + (size_t)m0 * DP, DP,
             g_Wh + ((size_t)DP + n0) * DV, DV,
             DV / 32, tid, lane, wm, wn);
    float* C = g_Sn + (size_t)b * DP * DP;
#pragma unroll
    for (int mt = 0; mt < 4; mt++)
#pragma unroll
        for (int nt = 0; nt < 4; nt++)
#pragma unroll
            for (int h = 0; h < 2; h++) {
                int r = m0 + wm * 64 + mt * 16 + (lane >> 2) + h * 8;
                int c = n0 + wn * 32 + nt * 8 + (lane & 3) * 2;
                float2 v = {acc[mt][nt][h*2], acc[mt][nt][h*2+1]};
                *(float2*)(C + (size_t)r * DP + c) = v;
            }
}

// ---------------- K4: V proj = Wv @ Vr, stored transposed (3-term, K=448) ----------------
__global__ void __launch_bounds__(256, 2)
projv_kernel() {
    extern __shared__ char smem[];
    u32 sb = smem_u32(smem), mb = sb + 3*STG;
    int tid = threadIdx.x, lane = tid & 31, wid = tid >> 5, wm = wid & 1, wn = wid >> 1;
    int b = blockIdx.z;
    int n0 = blockIdx.x * 128, m0 = blockIdx.y * 128;
    float acc[4][4][4] = {};
    gemm_main(sb, mb, acc,
              g_Wh + ((size_t)2 * DP + m0) * DV, g_Wl + ((size_t)2 * DP + m0) * DV, DV,
              g_Xrh + ((size_t)b * HW + n0) * DV, g_Xrl + ((size_t)b * HW + n0) * DV, DV,
              DV / 32, tid, lane, wm, wn);
    float* stg = (float*)smem;
    __syncthreads();
#pragma unroll
    for (int mt = 0; mt < 4; mt++)
#pragma unroll
        for (int nt = 0; nt < 4; nt++)
#pragma unroll
            for (int h = 0; h < 2; h++) {
                int rl = wm * 64 + mt * 16 + (lane >> 2) + h * 8;
                int cl = wn * 32 + nt * 8 + (lane & 3) * 2;
                stg[cl * 136 + rl]       = acc[mt][nt][h*2];
                stg[(cl + 1) * 136 + rl] = acc[mt][nt][h*2+1];
            }
    __syncthreads();
#pragma unroll
    for (int i = 0; i < 8; i++) {
        int task = i * 256 + tid, n = task >> 4, q = task & 15;
        float x[8];
#pragma unroll
        for (int j = 0; j < 8; j++) x[j] = stg[n * 136 + q * 8 + j];
        uint4 hi, lo; split8(x, hi, lo);
        size_t g = ((size_t)b * HW + n0 + n) * DP + m0 + q * 8;
        *(uint4*)(g_Vthi + g) = hi;
        *(uint4*)(g_Vtlo + g) = lo;
    }
}

// ---------------- K5: softmax; pos -> split alpha, neg -> bf16 alpha ----------------
__global__ void softmax_kernel() {
    const float inv_coef = 0.047245559126f;
    int r = blockIdx.x;
    int neg = r >= BSZ * DV, rr = neg ? r - BSZ * DV : r;
    int b = rr / DV, d = rr - b * DV;
    const float* S = (neg ? g_Sn : g_S) + ((size_t)b * DP + d) * DP;
    bf16* Oh = (neg ? g_Anhi : g_Aphi) + ((size_t)b * DP + d) * DP;
    bf16* Ol = g_Aplo + ((size_t)b * DP + d) * DP;
    int t = threadIdx.x;
    float a = S[t] * inv_coef;
    float bv = (t + 256 < DV) ? S[t + 256] * inv_coef : -1e30f;
    __shared__ float red[256];
    red[t] = fmaxf(a, bv);
    __syncthreads();
    for (int s = 128; s > 0; s >>= 1) { if (t < s) red[t] = fmaxf(red[t], red[t+s]); __syncthreads(); }
    float m = red[0];
    __syncthreads();
    float e0 = __expf(a - m), e1 = (t + 256 < DV) ? __expf(bv - m) : 0.f;
    red[t] = e0 + e1;
    __syncthreads();
    for (int s = 128; s > 0; s >>= 1) { if (t < s) red[t] += red[t+s]; __syncthreads(); }
    float inv = 1.f / red[0];
    float v0 = e0 * inv, v1 = e1 * inv;
    bf16 h0 = __float2bfloat16(v0);
    Oh[t] = h0;
    bf16 h1 = __float2bfloat16(v1);
    Oh[t + 256] = h1;                       // pad cols (>=448) stay exact 0
    if (!neg) {
        Ol[t] = __float2bfloat16(v0 - __bfloat162float(h0));
        Ol[t + 256] = __float2bfloat16(v1 - __bfloat162float(h1));
    }
}

// ---------------- K6a: out = Vs + alpha_pos @ Vp (3-term, K=448) ----------------
__global__ void __launch_bounds__(256, 2)
outpos_kernel(const float* __restrict__ Vs, float* __restrict__ out) {
    extern __shared__ char smem[];
    u32 sb = smem_u32(smem), mb = sb + 3*STG;
    int tid = threadIdx.x, lane = tid & 31, wid = tid >> 5, wm = wid & 1, wn = wid >> 1;
    int b = blockIdx.z;
    int m0 = blockIdx.y * 128, n0 = blockIdx.x * 128;
    float acc[4][4][4] = {};
    gemm_main(sb, mb, acc,
              g_Aphi + ((size_t)b * DP + m0) * DP, g_Aplo + ((size_t)b * DP + m0) * DP, DP,
              g_Vthi + ((size_t)b * HW + n0) * DP, g_Vtlo + ((size_t)b * HW + n0) * DP, DP,
              DV / 32, tid, lane, wm, wn);
#pragma unroll
    for (int mt = 0; mt < 4; mt++)
#pragma unroll
        for (int nt = 0; nt < 4; nt++)
#pragma unroll
            for (int h = 0; h < 2; h++) {
                int r = m0 + wm * 64 + mt * 16 + (lane >> 2) + h * 8;
                if (r < DV) {
                    int c = n0 + wn * 32 + nt * 8 + (lane & 3) * 2;
                    size_t g = ((size_t)b * DV + r) * HW + c;
                    float2 vs = *(const float2*)(Vs + g);
                    float2 o = {vs.x + acc[mt][nt][h*2], vs.y + acc[mt][nt][h*2+1]};
                    *(float2*)(out + g) = o;
                }
            }
}

// ---------------- K6b: v_neg = alpha_neg @ Vp (1-term) ; loss vs (out - Vs) ----------------
__global__ void __launch_bounds__(256, 2)
outneg_kernel(const float* __restrict__ Vs, const float* __restrict__ out) {
    extern __shared__ char smem[];
    u32 sb = smem_u32(smem), mb = sb + 3*STG1;
    int tid = threadIdx.x, lane = tid & 31, wid = tid >> 5, wm = wid & 1, wn = wid >> 1;
    int b = blockIdx.z;
    int m0 = blockIdx.y * 128, n0 = blockIdx.x * 128;
    float acc[4][4][4] = {};
    gemm_one(sb, mb, acc,
             g_Anhi + ((size_t)b * DP + m0) * DP, DP,
             g_Vthi + ((size_t)b * HW + n0) * DP, DP,
             DV / 32, tid, lane, wm, wn);
    float lsum = 0.f;
#pragma unroll
    for (int mt = 0; mt < 4; mt++)
#pragma unroll
        for (int nt = 0; nt < 4; nt++)
#pragma unroll
            for (int h = 0; h < 2; h++) {
                int r = m0 + wm * 64 + mt * 16 + (lane >> 2) + h * 8;
                if (r < DV) {
                    int c = n0 + wn * 32 + nt * 8 + (lane & 3) * 2;
                    size_t g = ((size_t)b * DV + r) * HW + c;
                    float2 o = *(const float2*)(out + g);
                    float2 vs = *(const float2*)(Vs + g);
                    lsum += fmaxf(0.f, -(o.x - vs.x) + acc[mt][nt][h*2]   + 12.f)
                          + fmaxf(0.f, -(o.y - vs.y) + acc[mt][nt][h*2+1] + 12.f);
                }
            }
    __shared__ float red[256];
    red[tid] = lsum;
    __syncthreads();
    for (int s = 128; s > 0; s >>= 1) { if (tid < s) red[tid] += red[tid+s]; __syncthreads(); }
    if (tid == 0) atomicAdd(&g_Ltr, (double)red[0]);
}

__global__ void zero_kernel() { g_Ltr = 0.0; }
__global__ void final_kernel(float* out, int idx) {
    out[idx] = (float)(g_Ltr * (1.0 / ((double)BSZ * DV * HW)));
}

extern "C" void kernel_launch(void* const* d_in, const int* in_sizes, int n_in,
                              void* d_out, int out_size) {
    const float* Vr = (const float*)d_in[0];
    const float* Vs = (const float*)d_in[1];
    const float* Wq = (const float*)d_in[2];
    const float* Wk = (const float*)d_in[3];
    const float* Wv = (const float*)d_in[4];
    float* out = (float*)d_out;

    static int cfg_done = 0;
    if (!cfg_done) {
        cudaFuncSetAttribute(mmp_kernel,    cudaFuncAttributeMaxDynamicSharedMemorySize, SM_GEMM);
        cudaFuncSetAttribute(mmn_kernel,    cudaFuncAttributeMaxDynamicSharedMemorySize, SM_G1);
        cudaFuncSetAttribute(tp_kernel,     cudaFuncAttributeMaxDynamicSharedMemorySize, SM_GEMM);
        cudaFuncSetAttribute(tn_kernel,     cudaFuncAttributeMaxDynamicSharedMemorySize, SM_G1);
        cudaFuncSetAttribute(sp_kernel,     cudaFuncAttributeMaxDynamicSharedMemorySize, SM_GEMM);
        cudaFuncSetAttribute(sn_kernel,     cudaFuncAttributeMaxDynamicSharedMemorySize, SM_G1);
        cudaFuncSetAttribute(projv_kernel,  cudaFuncAttributeMaxDynamicSharedMemorySize, SM_GEMM);
        cudaFuncSetAttribute(outpos_kernel, cudaFuncAttributeMaxDynamicSharedMemorySize, SM_GEMM);
        cudaFuncSetAttribute(outneg_kernel, cudaFuncAttributeMaxDynamicSharedMemorySize, SM_G1);
        cfg_done = 1;
    }

    zero_kernel<<<1, 1>>>();
    convw_kernel<<<(3 * DV * DV / 2 + 255) / 256, 256>>>(Wq, Wk, Wv);
    convy_kernel<<<dim3(HW / 512, DV, BSZ * 2), 256>>>(Vr, Vs);
    convx_kernel<<<dim3(HW / 32, DV / 32, BSZ), 256>>>(Vr);
    mmp_kernel<<<dim3(DP/128, DP/128, BSZ), 256, SM_GEMM>>>();
    mmn_kernel<<<dim3(DP/128, DP/128, BSZ), 256, SM_G1>>>();
    tp_kernel <<<dim3(DP/128, DP/128, BSZ), 256, SM_GEMM>>>();
    tn_kernel <<<dim3(DP/128, DP/128, BSZ), 256, SM_G1>>>();
    sp_kernel <<<dim3(DP/128, DP/128, BSZ), 256, SM_GEMM>>>();
    sn_kernel <<<dim3(DP/128, DP/128, BSZ), 256, SM_G1>>>();
    softmax_kernel<<<2 * BSZ * DV, 256>>>();
    projv_kernel <<<dim3(HW/128, DP/128, BSZ), 256, SM_GEMM>>>();
    outpos_kernel<<<dim3(HW/128, DP/128, BSZ), 256, SM_GEMM>>>(Vs, out);
    outneg_kernel<<<dim3(HW/128, DP/128, BSZ), 256, SM_G1>>>(Vs, out);
    final_kernel<<<1, 1>>>(out, out_size - 1);
}

// round 15
// speedup vs baseline: 1.4122x; 1.4122x over previous
#include <cuda_runtime.h>
#include <cuda_bf16.h>
#include <cstdint>

#define BSZ 16
#define DV  448
#define DP  512
#define HW  4096
typedef __nv_bfloat16 bf16;
typedef uint32_t u32;

#define TB32 8192                // one 128x32 bf16 tile
#define STG (4*TB32)             // Ah | Al | Bh | Bl = 32 KB
#define STG1 (2*TB32)            // A | B = 16 KB (1-term path)
#define SM_GEMM (3*STG + 128)    // 3 stages + mbarriers -> 2 CTAs/SM

// ---------------- scratch (zero-init; pad regions never written -> stay 0) ----------------
__device__ bf16 g_Wh[(size_t)3*DP*DV],  g_Wl[(size_t)3*DP*DV];
__device__ bf16 g_Yrh[(size_t)BSZ*DP*HW], g_Yrl[(size_t)BSZ*DP*HW];   // Vr split [b][c][h]
__device__ bf16 g_Ysh[(size_t)BSZ*DP*HW], g_Ysl[(size_t)BSZ*DP*HW];   // Vs split [b][c][h]
__device__ bf16 g_Xrh[(size_t)BSZ*HW*DV], g_Xrl[(size_t)BSZ*HW*DV];   // Vr^T split [b][h][c]
__device__ bf16 g_Mh[(size_t)BSZ*2*DP*DP], g_Ml[(size_t)BSZ*DP*DP];   // M' (neg half: hi only)
__device__ bf16 g_Th[(size_t)BSZ*2*DP*DP], g_Tl[(size_t)BSZ*DP*DP];   // T  (neg half: hi only)
__device__ bf16 g_Vthi[(size_t)BSZ*HW*DP], g_Vtlo[(size_t)BSZ*HW*DP]; // V^T = (Wv·Vr)^T
__device__ float g_S [(size_t)BSZ*DP*DP];
__device__ float g_Sn[(size_t)BSZ*DP*DP];
__device__ bf16 g_Aphi[(size_t)BSZ*DP*DP], g_Aplo[(size_t)BSZ*DP*DP];
__device__ bf16 g_Anhi[(size_t)BSZ*DP*DP];
__device__ double g_Ltr;

// ---------------- helpers ----------------
__device__ __forceinline__ u32 smem_u32(const void* p) {
    u32 a;
    asm("{ .reg .u64 t; cvta.to.shared.u64 t, %1; cvt.u32.u64 %0, t; }" : "=r"(a) : "l"(p));
    return a;
}
__device__ __forceinline__ u32 off32(int r, int c) {
    return (u32)(r * 64 + ((c ^ ((r >> 1) & 3)) << 4));
}
__device__ __forceinline__ void ldsm4(u32* r, u32 addr) {
    asm volatile("ldmatrix.sync.aligned.m8n8.x4.shared.b16 {%0,%1,%2,%3}, [%4];"
                 : "=r"(r[0]), "=r"(r[1]), "=r"(r[2]), "=r"(r[3]) : "r"(addr));
}
__device__ __forceinline__ void mma16816(float* c, const u32* a, u32 b0, u32 b1) {
    asm volatile("mma.sync.aligned.m16n8k16.row.col.f32.bf16.bf16.f32 "
                 "{%0,%1,%2,%3}, {%4,%5,%6,%7}, {%8,%9}, {%0,%1,%2,%3};"
                 : "+f"(c[0]), "+f"(c[1]), "+f"(c[2]), "+f"(c[3])
                 : "r"(a[0]), "r"(a[1]), "r"(a[2]), "r"(a[3]), "r"(b0), "r"(b1));
}
__device__ __forceinline__ void cpasync16(u32 sa, const void* g) {
    asm volatile("cp.async.cg.shared.global [%0], [%1], 16;" :: "r"(sa), "l"(g));
}
__device__ __forceinline__ void minit(u32 mb, u32 cnt) {
    asm volatile("mbarrier.init.shared.b64 [%0], %1;" :: "r"(mb), "r"(cnt) : "memory");
}
__device__ __forceinline__ void marrive(u32 mb) {
    asm volatile("mbarrier.arrive.shared.b64 _, [%0];" :: "r"(mb) : "memory");
}
__device__ __forceinline__ void cp_arrive(u32 mb) {
    asm volatile("cp.async.mbarrier.arrive.noinc.shared.b64 [%0];" :: "r"(mb) : "memory");
}
__device__ __forceinline__ void mwait(u32 mb, u32 ph) {
    asm volatile(
        "{\n\t.reg .pred P;\n\tWL%=:\n\t"
        "mbarrier.try_wait.parity.acquire.cta.shared::cta.b64 P, [%0], %1, 0x989680;\n\t"
        "@P bra WD%=;\n\tbra WL%=;\n\tWD%=:\n\t}" :: "r"(mb), "r"(ph) : "memory");
}

__device__ __forceinline__ void split2(float x0, float x1, u32& hw_, u32& lw) {
    bf16 h0 = __float2bfloat16(x0), h1 = __float2bfloat16(x1);
    bf16 l0 = __float2bfloat16(x0 - __bfloat162float(h0));
    bf16 l1 = __float2bfloat16(x1 - __bfloat162float(h1));
    hw_ = (u32)(*(uint16_t*)&h0) | ((u32)(*(uint16_t*)&h1) << 16);
    lw  = (u32)(*(uint16_t*)&l0) | ((u32)(*(uint16_t*)&l1) << 16);
}
__device__ __forceinline__ u32 pack2(float x0, float x1) {
    bf16 h0 = __float2bfloat16(x0), h1 = __float2bfloat16(x1);
    return (u32)(*(uint16_t*)&h0) | ((u32)(*(uint16_t*)&h1) << 16);
}
__device__ __forceinline__ void split8(const float* x, uint4& hi, uint4& lo) {
    u32 h[4], l[4];
#pragma unroll
    for (int j = 0; j < 4; j++) split2(x[2*j], x[2*j+1], h[j], l[j]);
    hi = make_uint4(h[0], h[1], h[2], h[3]);
    lo = make_uint4(l[0], l[1], l[2], l[3]);
}

// ---------------- producer: one 128x32 tile, 256 threads ----------------
__device__ __forceinline__ void issueT(u32 sbase, const bf16* __restrict__ g, int ld,
                                       int k0, int tid) {
#pragma unroll
    for (int i = 0; i < 2; i++) {
        int task = i * 256 + tid, r = task >> 2, c = task & 3;
        cpasync16(sbase + off32(r, c), g + (size_t)r * ld + k0 + c * 8);
    }
}
__device__ __forceinline__ void issue_stage(u32 base,
        const bf16* Ah, const bf16* Al, int lda,
        const bf16* Bh, const bf16* Bl, int ldb, int k0, int tid) {
    issueT(base,          Ah, lda, k0, tid);
    issueT(base + TB32,   Al, lda, k0, tid);
    issueT(base + 2*TB32, Bh, ldb, k0, tid);
    issueT(base + 3*TB32, Bl, ldb, k0, tid);
}

// ---------------- 3-term fragment load + mma ----------------
__device__ __forceinline__ void ld_frags(u32 base, int ks, int lane, int wm, int wn,
        u32 ah[4][4], u32 al[4][4], u32 bh[2][4], u32 bl[2][4]) {
    int lm = lane & 15, lk = lane >> 4;
    int ch = ks * 2 + lk;
#pragma unroll
    for (int mt = 0; mt < 4; mt++) {
        int r = wm * 64 + mt * 16 + lm;
        ldsm4(ah[mt], base +        off32(r, ch));
        ldsm4(al[mt], base + TB32 + off32(r, ch));
    }
#pragma unroll
    for (int nt = 0; nt < 2; nt++) {
        int r = wn * 32 + nt * 16 + lm;
        ldsm4(bh[nt], base + 2*TB32 + off32(r, ch));
        ldsm4(bl[nt], base + 3*TB32 + off32(r, ch));
    }
}
__device__ __forceinline__ void mma_frags(float acc[4][4][4],
        u32 ah[4][4], u32 al[4][4], u32 bh[2][4], u32 bl[2][4]) {
#pragma unroll
    for (int mt = 0; mt < 4; mt++)
#pragma unroll
        for (int nt = 0; nt < 4; nt++)
            mma16816(acc[mt][nt], ah[mt], bh[nt>>1][nt&1], bh[nt>>1][(nt&1)+2]);
#pragma unroll
    for (int mt = 0; mt < 4; mt++)
#pragma unroll
        for (int nt = 0; nt < 4; nt++)
            mma16816(acc[mt][nt], ah[mt], bl[nt>>1][nt&1], bl[nt>>1][(nt&1)+2]);
#pragma unroll
    for (int mt = 0; mt < 4; mt++)
#pragma unroll
        for (int nt = 0; nt < 4; nt++)
            mma16816(acc[mt][nt], al[mt], bh[nt>>1][nt&1], bh[nt>>1][(nt&1)+2]);
}

// ---------------- 3-term mbarrier-pipelined mainloop (CTA 128x128, k-tile 32) ----------
__device__ __forceinline__ void gemm_main(u32 sb, u32 mb, float acc[4][4][4],
        const bf16* Ah, const bf16* Al, int lda,
        const bf16* Bh, const bf16* Bl, int ldb,
        int NT, int tid, int lane, int wm, int wn) {
    if (tid == 0)
#pragma unroll
        for (int s = 0; s < 3; s++) { minit(mb + s*8, 256); minit(mb + 24 + s*8, 8); }
    __syncthreads();
#pragma unroll 1
    for (int s = 0; s < 2; s++) {
        issue_stage(sb + s * STG, Ah, Al, lda, Bh, Bl, ldb, s * 32, tid);
        cp_arrive(mb + s*8);
    }
#pragma unroll 1
    for (int it = 0; it < NT; it++) {
        int s = it % 3;
        mwait(mb + s*8, (it / 3) & 1);
        u32 base = sb + s * STG;
        u32 ah[4][4], al[4][4], bh[2][4], bl[2][4];
        ld_frags(base, 0, lane, wm, wn, ah, al, bh, bl);
        if (it + 2 < NT) {
            int pi = it + 2, ps = pi % 3;
            mwait(mb + 24 + ps*8, 1u ^ ((u32)(pi / 3) & 1));
            issue_stage(sb + ps * STG, Ah, Al, lda, Bh, Bl, ldb, pi * 32, tid);
            cp_arrive(mb + ps*8);
        }
        mma_frags(acc, ah, al, bh, bl);
        ld_frags(base, 1, lane, wm, wn, ah, al, bh, bl);
        if (lane == 0) marrive(mb + 24 + s*8);
        mma_frags(acc, ah, al, bh, bl);
    }
}

// ---------------- 1-term mainloop (plain bf16, CTA 128x128, k-tile 32) ----------------
__device__ __forceinline__ void gemm_one(u32 sb, u32 mb, float acc[4][4][4],
        const bf16* A, int lda, const bf16* B, int ldb,
        int NT, int tid, int lane, int wm, int wn) {
    if (tid == 0)
#pragma unroll
        for (int s = 0; s < 3; s++) { minit(mb + s*8, 256); minit(mb + 24 + s*8, 8); }
    __syncthreads();
#pragma unroll 1
    for (int s = 0; s < 2; s++) {
        issueT(sb + s * STG1,        A, lda, s * 32, tid);
        issueT(sb + s * STG1 + TB32, B, ldb, s * 32, tid);
        cp_arrive(mb + s*8);
    }
    int lm = lane & 15, lk = lane >> 4;
#pragma unroll 1
    for (int it = 0; it < NT; it++) {
        int s = it % 3;
        mwait(mb + s*8, (it / 3) & 1);
        u32 base = sb + s * STG1;
#pragma unroll
        for (int ks = 0; ks < 2; ks++) {
            int ch = ks * 2 + lk;
            u32 ah[4][4], bh[2][4];
#pragma unroll
            for (int mt = 0; mt < 4; mt++) {
                int r = wm * 64 + mt * 16 + lm;
                ldsm4(ah[mt], base + off32(r, ch));
            }
#pragma unroll
            for (int nt = 0; nt < 2; nt++) {
                int r = wn * 32 + nt * 16 + lm;
                ldsm4(bh[nt], base + TB32 + off32(r, ch));
            }
            if (ks == 0 && it + 2 < NT) {
                int pi = it + 2, ps = pi % 3;
                mwait(mb + 24 + ps*8, 1u ^ ((u32)(pi / 3) & 1));
                issueT(sb + ps * STG1,        A, lda, pi * 32, tid);
                issueT(sb + ps * STG1 + TB32, B, ldb, pi * 32, tid);
                cp_arrive(mb + ps*8);
            }
            if (ks == 1 && lane == 0) marrive(mb + 24 + s*8);
#pragma unroll
            for (int mt = 0; mt < 4; mt++)
#pragma unroll
                for (int nt = 0; nt < 4; nt++)
                    mma16816(acc[mt][nt], ah[mt], bh[nt>>1][nt&1], bh[nt>>1][(nt&1)+2]);
        }
    }
}

// ---------------- epilogues ----------------
__device__ __forceinline__ void store_split(bf16* Dh, bf16* Dl, size_t base, int ldc,
        float acc[4][4][4], int m0, int n0, int lane, int wm, int wn) {
#pragma unroll
    for (int mt = 0; mt < 4; mt++)
#pragma unroll
        for (int nt = 0; nt < 4; nt++)
#pragma unroll
            for (int h = 0; h < 2; h++) {
                int r = m0 + wm * 64 + mt * 16 + (lane >> 2) + h * 8;
                int c = n0 + wn * 32 + nt * 8 + (lane & 3) * 2;
                u32 hw_, lw;
                split2(acc[mt][nt][h*2], acc[mt][nt][h*2+1], hw_, lw);
                *(u32*)(Dh + base + (size_t)r * ldc + c) = hw_;
                *(u32*)(Dl + base + (size_t)r * ldc + c) = lw;
            }
}
__device__ __forceinline__ void store_hi(bf16* Dh, size_t base, int ldc,
        float acc[4][4][4], int m0, int n0, int lane, int wm, int wn) {
#pragma unroll
    for (int mt = 0; mt < 4; mt++)
#pragma unroll
        for (int nt = 0; nt < 4; nt++)
#pragma unroll
            for (int h = 0; h < 2; h++) {
                int r = m0 + wm * 64 + mt * 16 + (lane >> 2) + h * 8;
                int c = n0 + wn * 32 + nt * 8 + (lane & 3) * 2;
                *(u32*)(Dh + base + (size_t)r * ldc + c) =
                    pack2(acc[mt][nt][h*2], acc[mt][nt][h*2+1]);
            }
}
__device__ __forceinline__ void store_f32(float* C, float acc[4][4][4],
        int m0, int n0, int lane, int wm, int wn) {
#pragma unroll
    for (int mt = 0; mt < 4; mt++)
#pragma unroll
        for (int nt = 0; nt < 4; nt++)
#pragma unroll
            for (int h = 0; h < 2; h++) {
                int r = m0 + wm * 64 + mt * 16 + (lane >> 2) + h * 8;
                int c = n0 + wn * 32 + nt * 8 + (lane & 3) * 2;
                float2 v = {acc[mt][nt][h*2], acc[mt][nt][h*2+1]};
                *(float2*)(C + (size_t)r * DP + c) = v;
            }
}

// ---------------- pre-passes ----------------
__global__ void convw_kernel(const float* __restrict__ Wq, const float* __restrict__ Wk,
                             const float* __restrict__ Wv) {
    int t = blockIdx.x * 256 + threadIdx.x;
    const int half = DV * DV / 2;
    if (t >= 3 * half) return;
    int p = t / half, rem = t - p * half;
    int m = rem / (DV / 2), kp = rem - m * (DV / 2);
    const float* W = (p == 0) ? Wq : (p == 1) ? Wk : Wv;
    u32 hw_, lw;
    split2(W[m * DV + kp * 2], W[m * DV + kp * 2 + 1], hw_, lw);
    size_t g = ((size_t)p * DP + m) * DV + kp * 2;
    *(u32*)(g_Wh + g) = hw_;
    *(u32*)(g_Wl + g) = lw;
}

__global__ void convy_kernel(const float* __restrict__ Vr, const float* __restrict__ Vs) {
    int z = blockIdx.z, b = z >> 1, which = z & 1;
    const float* V = (which ? Vr : Vs) + (size_t)b * DV * HW;
    bf16* Yh = which ? g_Yrh : g_Ysh;
    bf16* Yl = which ? g_Yrl : g_Ysl;
    int c = blockIdx.y;
    int h = blockIdx.x * 512 + threadIdx.x * 2;
    float2 v = *(const float2*)(V + (size_t)c * HW + h);
    u32 hw_, lw;
    split2(v.x, v.y, hw_, lw);
    size_t g = ((size_t)b * DP + c) * HW + h;
    *(u32*)(Yh + g) = hw_;
    *(u32*)(Yl + g) = lw;
}

__global__ void convx_kernel(const float* __restrict__ Vr) {
    __shared__ float tile[32][33];
    int b = blockIdx.z;
    const float* V = Vr + (size_t)b * DV * HW;
    int h0 = blockIdx.x * 32, c0 = blockIdx.y * 32;
    int t = threadIdx.x, tx = t & 31, ty = t >> 5;
#pragma unroll
    for (int j = 0; j < 4; j++) {
        int cc = ty * 4 + j;
        tile[cc][tx] = V[(size_t)(c0 + cc) * HW + h0 + tx];
    }
    __syncthreads();
#pragma unroll
    for (int i = 0; i < 2; i++) {
        int task = i * 256 + t, hh = task >> 4, cp = task & 15;
        u32 hw_, lw;
        split2(tile[cp*2][hh], tile[cp*2+1][hh], hw_, lw);
        size_t g = ((size_t)b * HW + h0 + hh) * DV + c0 + cp * 2;
        *(u32*)(g_Xrh + g) = hw_;
        *(u32*)(g_Xrl + g) = lw;
    }
}

// ---------------- K1: M' pos(3-term)+neg(1-term) in one launch, K=4096 ----------------
__global__ void __launch_bounds__(256, 2)
mm_kernel() {
    extern __shared__ char smem[];
    u32 sb = smem_u32(smem), mb = sb + 3*STG;
    int tid = threadIdx.x, lane = tid & 31, wid = tid >> 5, wm = wid & 1, wn = wid >> 1;
    int z = blockIdx.z, b = z >> 1, neg = z & 1;
    int m0 = blockIdx.y * 128, n0 = blockIdx.x * 128;
    float acc[4][4][4] = {};
    if (!neg) {
        gemm_main(sb, mb, acc,
                  g_Yrh + ((size_t)b * DP + m0) * HW, g_Yrl + ((size_t)b * DP + m0) * HW, HW,
                  g_Ysh + ((size_t)b * DP + n0) * HW, g_Ysl + ((size_t)b * DP + n0) * HW, HW,
                  HW / 32, tid, lane, wm, wn);
        store_split(g_Mh, g_Ml, (size_t)b * DP * DP, DP, acc, m0, n0, lane, wm, wn);
    } else {
        int bk = (b + 1) & (BSZ - 1);
        gemm_one(sb, mb, acc,
                 g_Yrh + ((size_t)bk * DP + m0) * HW, HW,
                 g_Ysh + ((size_t)b  * DP + n0) * HW, HW,
                 HW / 32, tid, lane, wm, wn);
        store_hi(g_Mh, (size_t)(BSZ + b) * DP * DP, DP, acc, m0, n0, lane, wm, wn);
    }
}

// ---------------- K2: T = Wq @ M'^T pos+neg, K=448 ----------------
__global__ void __launch_bounds__(256, 2)
t_kernel() {
    extern __shared__ char smem[];
    u32 sb = smem_u32(smem), mb = sb + 3*STG;
    int tid = threadIdx.x, lane = tid & 31, wid = tid >> 5, wm = wid & 1, wn = wid >> 1;
    int z = blockIdx.z, b = z >> 1, neg = z & 1;
    int m0 = blockIdx.y * 128, n0 = blockIdx.x * 128;
    float acc[4][4][4] = {};
    if (!neg) {
        gemm_main(sb, mb, acc,
                  g_Wh + (size_t)m0 * DV, g_Wl + (size_t)m0 * DV, DV,
                  g_Mh + (size_t)b * DP * DP + (size_t)n0 * DP,
                  g_Ml + (size_t)b * DP * DP + (size_t)n0 * DP, DP,
                  DV / 32, tid, lane, wm, wn);
        store_split(g_Th, g_Tl, (size_t)b * DP * DP, DP, acc, m0, n0, lane, wm, wn);
    } else {
        gemm_one(sb, mb, acc,
                 g_Wh + (size_t)m0 * DV, DV,
                 g_Mh + (size_t)(BSZ + b) * DP * DP + (size_t)n0 * DP, DP,
                 DV / 32, tid, lane, wm, wn);
        store_hi(g_Th, (size_t)(BSZ + b) * DP * DP, DP, acc, m0, n0, lane, wm, wn);
    }
}

// ---------------- K3: S = T @ Wk^T pos+neg, K=448 ----------------
__global__ void __launch_bounds__(256, 2)
s_kernel() {
    extern __shared__ char smem[];
    u32 sb = smem_u32(smem), mb = sb + 3*STG;
    int tid = threadIdx.x, lane = tid & 31, wid = tid >> 5, wm = wid & 1, wn = wid >> 1;
    int z = blockIdx.z, b = z >> 1, neg = z & 1;
    int m0 = blockIdx.y * 128, n0 = blockIdx.x * 128;
    float acc[4][4][4] = {};
    if (!neg) {
        gemm_main(sb, mb, acc,
                  g_Th + (size_t)b * DP * DP + (size_t)m0 * DP,
                  g_Tl + (size_t)b * DP * DP + (size_t)m0 * DP, DP,
                  g_Wh + ((size_t)DP + n0) * DV, g_Wl + ((size_t)DP + n0) * DV, DV,
                  DV / 32, tid, lane, wm, wn);
        store_f32(g_S + (size_t)b * DP * DP, acc, m0, n0, lane, wm, wn);
    } else {
        gemm_one(sb, mb, acc,
                 g_Th + (size_t)(BSZ + b) * DP * DP + (size_t)m0 * DP, DP,
                 g_Wh + ((size_t)DP + n0) * DV, DV,
                 DV / 32, tid, lane, wm, wn);
        store_f32(g_Sn + (size_t)b * DP * DP, acc, m0, n0, lane, wm, wn);
    }
}

// ---------------- K4: V proj = Wv @ Vr, stored transposed (3-term, K=448) ----------------
__global__ void __launch_bounds__(256, 2)
projv_kernel() {
    extern __shared__ char smem[];
    u32 sb = smem_u32(smem), mb = sb + 3*STG;
    int tid = threadIdx.x, lane = tid & 31, wid = tid >> 5, wm = wid & 1, wn = wid >> 1;
    int b = blockIdx.z;
    int n0 = blockIdx.x * 128, m0 = blockIdx.y * 128;
    float acc[4][4][4] = {};
    gemm_main(sb, mb, acc,
              g_Wh + ((size_t)2 * DP + m0) * DV, g_Wl + ((size_t)2 * DP + m0) * DV, DV,
              g_Xrh + ((size_t)b * HW + n0) * DV, g_Xrl + ((size_t)b * HW + n0) * DV, DV,
              DV / 32, tid, lane, wm, wn);
    float* stg = (float*)smem;
    __syncthreads();
#pragma unroll
    for (int mt = 0; mt < 4; mt++)
#pragma unroll
        for (int nt = 0; nt < 4; nt++)
#pragma unroll
            for (int h = 0; h < 2; h++) {
                int rl = wm * 64 + mt * 16 + (lane >> 2) + h * 8;
                int cl = wn * 32 + nt * 8 + (lane & 3) * 2;
                stg[cl * 136 + rl]       = acc[mt][nt][h*2];
                stg[(cl + 1) * 136 + rl] = acc[mt][nt][h*2+1];
            }
    __syncthreads();
#pragma unroll
    for (int i = 0; i < 8; i++) {
        int task = i * 256 + tid, n = task >> 4, q = task & 15;
        float x[8];
#pragma unroll
        for (int j = 0; j < 8; j++) x[j] = stg[n * 136 + q * 8 + j];
        uint4 hi, lo; split8(x, hi, lo);
        size_t g = ((size_t)b * HW + n0 + n) * DP + m0 + q * 8;
        *(uint4*)(g_Vthi + g) = hi;
        *(uint4*)(g_Vtlo + g) = lo;
    }
}

// ---------------- K5: softmax; pos -> split alpha, neg -> bf16 alpha ----------------
__global__ void softmax_kernel() {
    const float inv_coef = 0.047245559126f;
    int r = blockIdx.x;
    int neg = r >= BSZ * DV, rr = neg ? r - BSZ * DV : r;
    int b = rr / DV, d = rr - b * DV;
    const float* S = (neg ? g_Sn : g_S) + ((size_t)b * DP + d) * DP;
    bf16* Oh = (neg ? g_Anhi : g_Aphi) + ((size_t)b * DP + d) * DP;
    bf16* Ol = g_Aplo + ((size_t)b * DP + d) * DP;
    int t = threadIdx.x;
    float a = S[t] * inv_coef;
    float bv = (t + 256 < DV) ? S[t + 256] * inv_coef : -1e30f;
    __shared__ float red[256];
    red[t] = fmaxf(a, bv);
    __syncthreads();
    for (int s = 128; s > 0; s >>= 1) { if (t < s) red[t] = fmaxf(red[t], red[t+s]); __syncthreads(); }
    float m = red[0];
    __syncthreads();
    float e0 = __expf(a - m), e1 = (t + 256 < DV) ? __expf(bv - m) : 0.f;
    red[t] = e0 + e1;
    __syncthreads();
    for (int s = 128; s > 0; s >>= 1) { if (t < s) red[t] += red[t+s]; __syncthreads(); }
    float inv = 1.f / red[0];
    float v0 = e0 * inv, v1 = e1 * inv;
    bf16 h0 = __float2bfloat16(v0);
    Oh[t] = h0;
    bf16 h1 = __float2bfloat16(v1);
    Oh[t + 256] = h1;                       // pad cols (>=448) stay exact 0
    if (!neg) {
        Ol[t] = __float2bfloat16(v0 - __bfloat162float(h0));
        Ol[t + 256] = __float2bfloat16(v1 - __bfloat162float(h1));
    }
}

// ---------------- K6a: out = Vs + alpha_pos @ Vp (3-term, K=448) ----------------
__global__ void __launch_bounds__(256, 2)
outpos_kernel(const float* __restrict__ Vs, float* __restrict__ out) {
    extern __shared__ char smem[];
    u32 sb = smem_u32(smem), mb = sb + 3*STG;
    int tid = threadIdx.x, lane = tid & 31, wid = tid >> 5, wm = wid & 1, wn = wid >> 1;
    int b = blockIdx.z;
    int m0 = blockIdx.y * 128, n0 = blockIdx.x * 128;
    float acc[4][4][4] = {};
    gemm_main(sb, mb, acc,
              g_Aphi + ((size_t)b * DP + m0) * DP, g_Aplo + ((size_t)b * DP + m0) * DP, DP,
              g_Vthi + ((size_t)b * HW + n0) * DP, g_Vtlo + ((size_t)b * HW + n0) * DP, DP,
              DV / 32, tid, lane, wm, wn);
#pragma unroll
    for (int mt = 0; mt < 4; mt++)
#pragma unroll
        for (int nt = 0; nt < 4; nt++)
#pragma unroll
            for (int h = 0; h < 2; h++) {
                int r = m0 + wm * 64 + mt * 16 + (lane >> 2) + h * 8;
                if (r < DV) {
                    int c = n0 + wn * 32 + nt * 8 + (lane & 3) * 2;
                    size_t g = ((size_t)b * DV + r) * HW + c;
                    float2 vs = *(const float2*)(Vs + g);
                    float2 o = {vs.x + acc[mt][nt][h*2], vs.y + acc[mt][nt][h*2+1]};
                    *(float2*)(out + g) = o;
                }
            }
}

// ---------------- K6b: v_neg = alpha_neg @ Vp (1-term) ; loss vs (out - Vs) ----------------
__global__ void __launch_bounds__(256, 2)
outneg_kernel(const float* __restrict__ Vs, const float* __restrict__ out) {
    extern __shared__ char smem[];
    u32 sb = smem_u32(smem), mb = sb + 3*STG1;
    int tid = threadIdx.x, lane = tid & 31, wid = tid >> 5, wm = wid & 1, wn = wid >> 1;
    int b = blockIdx.z;
    int m0 = blockIdx.y * 128, n0 = blockIdx.x * 128;
    float acc[4][4][4] = {};
    gemm_one(sb, mb, acc,
             g_Anhi + ((size_t)b * DP + m0) * DP, DP,
             g_Vthi + ((size_t)b * HW + n0) * DP, DP,
             DV / 32, tid, lane, wm, wn);
    float lsum = 0.f;
#pragma unroll
    for (int mt = 0; mt < 4; mt++)
#pragma unroll
        for (int nt = 0; nt < 4; nt++)
#pragma unroll
            for (int h = 0; h < 2; h++) {
                int r = m0 + wm * 64 + mt * 16 + (lane >> 2) + h * 8;
                if (r < DV) {
                    int c = n0 + wn * 32 + nt * 8 + (lane & 3) * 2;
                    size_t g = ((size_t)b * DV + r) * HW + c;
                    float2 o = *(const float2*)(out + g);
                    float2 vs = *(const float2*)(Vs + g);
                    lsum += fmaxf(0.f, -(o.x - vs.x) + acc[mt][nt][h*2]   + 12.f)
                          + fmaxf(0.f, -(o.y - vs.y) + acc[mt][nt][h*2+1] + 12.f);
                }
            }
    __shared__ float red[256];
    red[tid] = lsum;
    __syncthreads();
    for (int s = 128; s > 0; s >>= 1) { if (tid < s) red[tid] += red[tid+s]; __syncthreads(); }
    if (tid == 0) atomicAdd(&g_Ltr, (double)red[0]);
}

__global__ void zero_kernel() { g_Ltr = 0.0; }
__global__ void final_kernel(float* out, int idx) {
    out[idx] = (float)(g_Ltr * (1.0 / ((double)BSZ * DV * HW)));
}

extern "C" void kernel_launch(void* const* d_in, const int* in_sizes, int n_in,
                              void* d_out, int out_size) {
    const float* Vr = (const float*)d_in[0];
    const float* Vs = (const float*)d_in[1];
    const float* Wq = (const float*)d_in[2];
    const float* Wk = (const float*)d_in[3];
    const float* Wv = (const float*)d_in[4];
    float* out = (float*)d_out;

    static int cfg_done = 0;
    if (!cfg_done) {
        cudaFuncSetAttribute(mm_kernel,     cudaFuncAttributeMaxDynamicSharedMemorySize, SM_GEMM);
        cudaFuncSetAttribute(t_kernel,      cudaFuncAttributeMaxDynamicSharedMemorySize, SM_GEMM);
        cudaFuncSetAttribute(s_kernel,      cudaFuncAttributeMaxDynamicSharedMemorySize, SM_GEMM);
        cudaFuncSetAttribute(projv_kernel,  cudaFuncAttributeMaxDynamicSharedMemorySize, SM_GEMM);
        cudaFuncSetAttribute(outpos_kernel, cudaFuncAttributeMaxDynamicSharedMemorySize, SM_GEMM);
        cudaFuncSetAttribute(outneg_kernel, cudaFuncAttributeMaxDynamicSharedMemorySize, SM_GEMM);
        cfg_done = 1;
    }

    zero_kernel<<<1, 1>>>();
    convw_kernel<<<(3 * DV * DV / 2 + 255) / 256, 256>>>(Wq, Wk, Wv);
    convy_kernel<<<dim3(HW / 512, DV, BSZ * 2), 256>>>(Vr, Vs);
    convx_kernel<<<dim3(HW / 32, DV / 32, BSZ), 256>>>(Vr);
    mm_kernel<<<dim3(DP/128, DP/128, BSZ*2), 256, SM_GEMM>>>();
    t_kernel <<<dim3(DP/128, DP/128, BSZ*2), 256, SM_GEMM>>>();
    s_kernel <<<dim3(DP/128, DP/128, BSZ*2), 256, SM_GEMM>>>();
    softmax_kernel<<<2 * BSZ * DV, 256>>>();
    projv_kernel <<<dim3(HW/128, DP/128, BSZ), 256, SM_GEMM>>>();
    outpos_kernel<<<dim3(HW/128, DP/128, BSZ), 256, SM_GEMM>>>(Vs, out);
    outneg_kernel<<<dim3(HW/128, DP/128, BSZ), 256, SM_GEMM>>>(Vs, out);
    final_kernel<<<1, 1>>>(out, out_size - 1);
}

// round 16
// speedup vs baseline: 1.6044x; 1.1361x over previous
#include <cuda_runtime.h>
#include <cuda_bf16.h>
#include <cstdint>

#define BSZ 16
#define DV  448
#define DP  512
#define HW  4096
typedef __nv_bfloat16 bf16;
typedef uint32_t u32;

#define TB32 8192                // one 128x32 bf16 tile
#define STG (4*TB32)             // Ah | Al | Bh | Bl = 32 KB
#define STG1 (2*TB32)            // A | B = 16 KB (1-term path)
#define SM_GEMM (3*STG + 128)    // 3 stages + mbarriers -> 2 CTAs/SM

// ---------------- scratch (zero-init; pad regions never written -> stay 0) ----------------
__device__ bf16 g_Wh[(size_t)3*DP*DV],  g_Wl[(size_t)3*DP*DV];
__device__ bf16 g_WvTh[(size_t)DP*DV],  g_WvTl[(size_t)DP*DV];        // Wv^T split [c][e]
__device__ bf16 g_Yrh[(size_t)BSZ*DP*HW], g_Yrl[(size_t)BSZ*DP*HW];   // Vr split [b][c][h]
__device__ bf16 g_Ysh[(size_t)BSZ*DP*HW], g_Ysl[(size_t)BSZ*DP*HW];   // Vs split [b][c][h]
__device__ bf16 g_Xrh[(size_t)BSZ*HW*DV], g_Xrl[(size_t)BSZ*HW*DV];   // Vr^T split [b][h][c]
__device__ bf16 g_Mh[(size_t)BSZ*2*DP*DP], g_Ml[(size_t)BSZ*DP*DP];   // M' (neg half: hi only)
__device__ bf16 g_Th[(size_t)BSZ*2*DP*DP], g_Tl[(size_t)BSZ*DP*DP];   // T  (neg half: hi only)
__device__ bf16 g_B2h[(size_t)BSZ*2*DP*DP], g_B2l[(size_t)BSZ*DP*DP]; // B2 = alpha @ Wv
__device__ float g_S [(size_t)BSZ*DP*DP];
__device__ float g_Sn[(size_t)BSZ*DP*DP];
__device__ bf16 g_Aphi[(size_t)BSZ*DP*DP], g_Aplo[(size_t)BSZ*DP*DP];
__device__ bf16 g_Anhi[(size_t)BSZ*DP*DP];
__device__ double g_Ltr;

// ---------------- helpers ----------------
__device__ __forceinline__ u32 smem_u32(const void* p) {
    u32 a;
    asm("{ .reg .u64 t; cvta.to.shared.u64 t, %1; cvt.u32.u64 %0, t; }" : "=r"(a) : "l"(p));
    return a;
}
__device__ __forceinline__ u32 off32(int r, int c) {
    return (u32)(r * 64 + ((c ^ ((r >> 1) & 3)) << 4));
}
__device__ __forceinline__ void ldsm4(u32* r, u32 addr) {
    asm volatile("ldmatrix.sync.aligned.m8n8.x4.shared.b16 {%0,%1,%2,%3}, [%4];"
                 : "=r"(r[0]), "=r"(r[1]), "=r"(r[2]), "=r"(r[3]) : "r"(addr));
}
__device__ __forceinline__ void mma16816(float* c, const u32* a, u32 b0, u32 b1) {
    asm volatile("mma.sync.aligned.m16n8k16.row.col.f32.bf16.bf16.f32 "
                 "{%0,%1,%2,%3}, {%4,%5,%6,%7}, {%8,%9}, {%0,%1,%2,%3};"
                 : "+f"(c[0]), "+f"(c[1]), "+f"(c[2]), "+f"(c[3])
                 : "r"(a[0]), "r"(a[1]), "r"(a[2]), "r"(a[3]), "r"(b0), "r"(b1));
}
__device__ __forceinline__ void cpasync16(u32 sa, const void* g) {
    asm volatile("cp.async.cg.shared.global [%0], [%1], 16;" :: "r"(sa), "l"(g));
}
__device__ __forceinline__ void minit(u32 mb, u32 cnt) {
    asm volatile("mbarrier.init.shared.b64 [%0], %1;" :: "r"(mb), "r"(cnt) : "memory");
}
__device__ __forceinline__ void marrive(u32 mb) {
    asm volatile("mbarrier.arrive.shared.b64 _, [%0];" :: "r"(mb) : "memory");
}
__device__ __forceinline__ void cp_arrive(u32 mb) {
    asm volatile("cp.async.mbarrier.arrive.noinc.shared.b64 [%0];" :: "r"(mb) : "memory");
}
__device__ __forceinline__ void mwait(u32 mb, u32 ph) {
    asm volatile(
        "{\n\t.reg .pred P;\n\tWL%=:\n\t"
        "mbarrier.try_wait.parity.acquire.cta.shared::cta.b64 P, [%0], %1, 0x989680;\n\t"
        "@P bra WD%=;\n\tbra WL%=;\n\tWD%=:\n\t}" :: "r"(mb), "r"(ph) : "memory");
}

__device__ __forceinline__ void split2(float x0, float x1, u32& hw_, u32& lw) {
    bf16 h0 = __float2bfloat16(x0), h1 = __float2bfloat16(x1);
    bf16 l0 = __float2bfloat16(x0 - __bfloat162float(h0));
    bf16 l1 = __float2bfloat16(x1 - __bfloat162float(h1));
    hw_ = (u32)(*(uint16_t*)&h0) | ((u32)(*(uint16_t*)&h1) << 16);
    lw  = (u32)(*(uint16_t*)&l0) | ((u32)(*(uint16_t*)&l1) << 16);
}
__device__ __forceinline__ u32 pack2(float x0, float x1) {
    bf16 h0 = __float2bfloat16(x0), h1 = __float2bfloat16(x1);
    return (u32)(*(uint16_t*)&h0) | ((u32)(*(uint16_t*)&h1) << 16);
}

// ---------------- producer: one 128x32 tile, 256 threads ----------------
__device__ __forceinline__ void issueT(u32 sbase, const bf16* __restrict__ g, int ld,
                                       int k0, int tid) {
#pragma unroll
    for (int i = 0; i < 2; i++) {
        int task = i * 256 + tid, r = task >> 2, c = task & 3;
        cpasync16(sbase + off32(r, c), g + (size_t)r * ld + k0 + c * 8);
    }
}
__device__ __forceinline__ void issue_stage(u32 base,
        const bf16* Ah, const bf16* Al, int lda,
        const bf16* Bh, const bf16* Bl, int ldb, int k0, int tid) {
    issueT(base,          Ah, lda, k0, tid);
    issueT(base + TB32,   Al, lda, k0, tid);
    issueT(base + 2*TB32, Bh, ldb, k0, tid);
    issueT(base + 3*TB32, Bl, ldb, k0, tid);
}

// ---------------- 3-term fragment load + mma ----------------
__device__ __forceinline__ void ld_frags(u32 base, int ks, int lane, int wm, int wn,
        u32 ah[4][4], u32 al[4][4], u32 bh[2][4], u32 bl[2][4]) {
    int lm = lane & 15, lk = lane >> 4;
    int ch = ks * 2 + lk;
#pragma unroll
    for (int mt = 0; mt < 4; mt++) {
        int r = wm * 64 + mt * 16 + lm;
        ldsm4(ah[mt], base +        off32(r, ch));
        ldsm4(al[mt], base + TB32 + off32(r, ch));
    }
#pragma unroll
    for (int nt = 0; nt < 2; nt++) {
        int r = wn * 32 + nt * 16 + lm;
        ldsm4(bh[nt], base + 2*TB32 + off32(r, ch));
        ldsm4(bl[nt], base + 3*TB32 + off32(r, ch));
    }
}
__device__ __forceinline__ void mma_frags(float acc[4][4][4],
        u32 ah[4][4], u32 al[4][4], u32 bh[2][4], u32 bl[2][4]) {
#pragma unroll
    for (int mt = 0; mt < 4; mt++)
#pragma unroll
        for (int nt = 0; nt < 4; nt++)
            mma16816(acc[mt][nt], ah[mt], bh[nt>>1][nt&1], bh[nt>>1][(nt&1)+2]);
#pragma unroll
    for (int mt = 0; mt < 4; mt++)
#pragma unroll
        for (int nt = 0; nt < 4; nt++)
            mma16816(acc[mt][nt], ah[mt], bl[nt>>1][nt&1], bl[nt>>1][(nt&1)+2]);
#pragma unroll
    for (int mt = 0; mt < 4; mt++)
#pragma unroll
        for (int nt = 0; nt < 4; nt++)
            mma16816(acc[mt][nt], al[mt], bh[nt>>1][nt&1], bh[nt>>1][(nt&1)+2]);
}

// ---------------- 3-term mbarrier-pipelined mainloop (CTA 128x128, k-tile 32) ----------
__device__ __forceinline__ void gemm_main(u32 sb, u32 mb, float acc[4][4][4],
        const bf16* Ah, const bf16* Al, int lda,
        const bf16* Bh, const bf16* Bl, int ldb,
        int NT, int tid, int lane, int wm, int wn) {
    if (tid == 0)
#pragma unroll
        for (int s = 0; s < 3; s++) { minit(mb + s*8, 256); minit(mb + 24 + s*8, 8); }
    __syncthreads();
#pragma unroll 1
    for (int s = 0; s < 2; s++) {
        issue_stage(sb + s * STG, Ah, Al, lda, Bh, Bl, ldb, s * 32, tid);
        cp_arrive(mb + s*8);
    }
#pragma unroll 1
    for (int it = 0; it < NT; it++) {
        int s = it % 3;
        mwait(mb + s*8, (it / 3) & 1);
        u32 base = sb + s * STG;
        u32 ah[4][4], al[4][4], bh[2][4], bl[2][4];
        ld_frags(base, 0, lane, wm, wn, ah, al, bh, bl);
        if (it + 2 < NT) {
            int pi = it + 2, ps = pi % 3;
            mwait(mb + 24 + ps*8, 1u ^ ((u32)(pi / 3) & 1));
            issue_stage(sb + ps * STG, Ah, Al, lda, Bh, Bl, ldb, pi * 32, tid);
            cp_arrive(mb + ps*8);
        }
        mma_frags(acc, ah, al, bh, bl);
        ld_frags(base, 1, lane, wm, wn, ah, al, bh, bl);
        if (lane == 0) marrive(mb + 24 + s*8);
        mma_frags(acc, ah, al, bh, bl);
    }
}

// ---------------- 1-term mainloop (plain bf16, CTA 128x128, k-tile 32) ----------------
__device__ __forceinline__ void gemm_one(u32 sb, u32 mb, float acc[4][4][4],
        const bf16* A, int lda, const bf16* B, int ldb,
        int NT, int tid, int lane, int wm, int wn) {
    if (tid == 0)
#pragma unroll
        for (int s = 0; s < 3; s++) { minit(mb + s*8, 256); minit(mb + 24 + s*8, 8); }
    __syncthreads();
#pragma unroll 1
    for (int s = 0; s < 2; s++) {
        issueT(sb + s * STG1,        A, lda, s * 32, tid);
        issueT(sb + s * STG1 + TB32, B, ldb, s * 32, tid);
        cp_arrive(mb + s*8);
    }
    int lm = lane & 15, lk = lane >> 4;
#pragma unroll 1
    for (int it = 0; it < NT; it++) {
        int s = it % 3;
        mwait(mb + s*8, (it / 3) & 1);
        u32 base = sb + s * STG1;
#pragma unroll
        for (int ks = 0; ks < 2; ks++) {
            int ch = ks * 2 + lk;
            u32 ah[4][4], bh[2][4];
#pragma unroll
            for (int mt = 0; mt < 4; mt++) {
                int r = wm * 64 + mt * 16 + lm;
                ldsm4(ah[mt], base + off32(r, ch));
            }
#pragma unroll
            for (int nt = 0; nt < 2; nt++) {
                int r = wn * 32 + nt * 16 + lm;
                ldsm4(bh[nt], base + TB32 + off32(r, ch));
            }
            if (ks == 0 && it + 2 < NT) {
                int pi = it + 2, ps = pi % 3;
                mwait(mb + 24 + ps*8, 1u ^ ((u32)(pi / 3) & 1));
                issueT(sb + ps * STG1,        A, lda, pi * 32, tid);
                issueT(sb + ps * STG1 + TB32, B, ldb, pi * 32, tid);
                cp_arrive(mb + ps*8);
            }
            if (ks == 1 && lane == 0) marrive(mb + 24 + s*8);
#pragma unroll
            for (int mt = 0; mt < 4; mt++)
#pragma unroll
                for (int nt = 0; nt < 4; nt++)
                    mma16816(acc[mt][nt], ah[mt], bh[nt>>1][nt&1], bh[nt>>1][(nt&1)+2]);
        }
    }
}

// ---------------- epilogues ----------------
__device__ __forceinline__ void store_split(bf16* Dh, bf16* Dl, size_t base, int ldc,
        float acc[4][4][4], int m0, int n0, int lane, int wm, int wn) {
#pragma unroll
    for (int mt = 0; mt < 4; mt++)
#pragma unroll
        for (int nt = 0; nt < 4; nt++)
#pragma unroll
            for (int h = 0; h < 2; h++) {
                int r = m0 + wm * 64 + mt * 16 + (lane >> 2) + h * 8;
                int c = n0 + wn * 32 + nt * 8 + (lane & 3) * 2;
                u32 hw_, lw;
                split2(acc[mt][nt][h*2], acc[mt][nt][h*2+1], hw_, lw);
                *(u32*)(Dh + base + (size_t)r * ldc + c) = hw_;
                *(u32*)(Dl + base + (size_t)r * ldc + c) = lw;
            }
}
__device__ __forceinline__ void store_hi(bf16* Dh, size_t base, int ldc,
        float acc[4][4][4], int m0, int n0, int lane, int wm, int wn) {
#pragma unroll
    for (int mt = 0; mt < 4; mt++)
#pragma unroll
        for (int nt = 0; nt < 4; nt++)
#pragma unroll
            for (int h = 0; h < 2; h++) {
                int r = m0 + wm * 64 + mt * 16 + (lane >> 2) + h * 8;
                int c = n0 + wn * 32 + nt * 8 + (lane & 3) * 2;
                *(u32*)(Dh + base + (size_t)r * ldc + c) =
                    pack2(acc[mt][nt][h*2], acc[mt][nt][h*2+1]);
            }
}
__device__ __forceinline__ void store_f32(float* C, float acc[4][4][4],
        int m0, int n0, int lane, int wm, int wn) {
#pragma unroll
    for (int mt = 0; mt < 4; mt++)
#pragma unroll
        for (int nt = 0; nt < 4; nt++)
#pragma unroll
            for (int h = 0; h < 2; h++) {
                int r = m0 + wm * 64 + mt * 16 + (lane >> 2) + h * 8;
                int c = n0 + wn * 32 + nt * 8 + (lane & 3) * 2;
                float2 v = {acc[mt][nt][h*2], acc[mt][nt][h*2+1]};
                *(float2*)(C + (size_t)r * DP + c) = v;
            }
}

// ---------------- pre-passes ----------------
__global__ void convw_kernel(const float* __restrict__ Wq, const float* __restrict__ Wk,
                             const float* __restrict__ Wv) {
    int t = blockIdx.x * 256 + threadIdx.x;
    const int half = DV * DV / 2;
    if (t >= 3 * half) return;
    int p = t / half, rem = t - p * half;
    int m = rem / (DV / 2), kp = rem - m * (DV / 2);
    const float* W = (p == 0) ? Wq : (p == 1) ? Wk : Wv;
    float x0 = W[m * DV + kp * 2], x1 = W[m * DV + kp * 2 + 1];
    bf16 h0 = __float2bfloat16(x0), h1 = __float2bfloat16(x1);
    bf16 l0 = __float2bfloat16(x0 - __bfloat162float(h0));
    bf16 l1 = __float2bfloat16(x1 - __bfloat162float(h1));
    size_t g = ((size_t)p * DP + m) * DV + kp * 2;
    *(u32*)(g_Wh + g) = (u32)(*(uint16_t*)&h0) | ((u32)(*(uint16_t*)&h1) << 16);
    *(u32*)(g_Wl + g) = (u32)(*(uint16_t*)&l0) | ((u32)(*(uint16_t*)&l1) << 16);
    if (p == 2) {  // also Wv^T[c][e] for the B2 GEMM
        int c0 = kp * 2;
        g_WvTh[(size_t)c0 * DV + m] = h0;       g_WvTl[(size_t)c0 * DV + m] = l0;
        g_WvTh[(size_t)(c0 + 1) * DV + m] = h1; g_WvTl[(size_t)(c0 + 1) * DV + m] = l1;
    }
}

__global__ void convy_kernel(const float* __restrict__ Vr, const float* __restrict__ Vs) {
    int z = blockIdx.z, b = z >> 1, which = z & 1;
    const float* V = (which ? Vr : Vs) + (size_t)b * DV * HW;
    bf16* Yh = which ? g_Yrh : g_Ysh;
    bf16* Yl = which ? g_Yrl : g_Ysl;
    int c = blockIdx.y;
    int h = blockIdx.x * 512 + threadIdx.x * 2;
    float2 v = *(const float2*)(V + (size_t)c * HW + h);
    u32 hw_, lw;
    split2(v.x, v.y, hw_, lw);
    size_t g = ((size_t)b * DP + c) * HW + h;
    *(u32*)(Yh + g) = hw_;
    *(u32*)(Yl + g) = lw;
}

__global__ void convx_kernel(const float* __restrict__ Vr) {
    __shared__ float tile[32][33];
    int b = blockIdx.z;
    const float* V = Vr + (size_t)b * DV * HW;
    int h0 = blockIdx.x * 32, c0 = blockIdx.y * 32;
    int t = threadIdx.x, tx = t & 31, ty = t >> 5;
#pragma unroll
    for (int j = 0; j < 4; j++) {
        int cc = ty * 4 + j;
        tile[cc][tx] = V[(size_t)(c0 + cc) * HW + h0 + tx];
    }
    __syncthreads();
#pragma unroll
    for (int i = 0; i < 2; i++) {
        int task = i * 256 + t, hh = task >> 4, cp = task & 15;
        u32 hw_, lw;
        split2(tile[cp*2][hh], tile[cp*2+1][hh], hw_, lw);
        size_t g = ((size_t)b * HW + h0 + hh) * DV + c0 + cp * 2;
        *(u32*)(g_Xrh + g) = hw_;
        *(u32*)(g_Xrl + g) = lw;
    }
}

// ---------------- K1: M' pos(3-term)+neg(1-term) in one launch, K=4096 ----------------
__global__ void __launch_bounds__(256, 2)
mm_kernel() {
    extern __shared__ char smem[];
    u32 sb = smem_u32(smem), mb = sb + 3*STG;
    int tid = threadIdx.x, lane = tid & 31, wid = tid >> 5, wm = wid & 1, wn = wid >> 1;
    int z = blockIdx.z, b = z >> 1, neg = z & 1;
    int m0 = blockIdx.y * 128, n0 = blockIdx.x * 128;
    float acc[4][4][4] = {};
    if (!neg) {
        gemm_main(sb, mb, acc,
                  g_Yrh + ((size_t)b * DP + m0) * HW, g_Yrl + ((size_t)b * DP + m0) * HW, HW,
                  g_Ysh + ((size_t)b * DP + n0) * HW, g_Ysl + ((size_t)b * DP + n0) * HW, HW,
                  HW / 32, tid, lane, wm, wn);
        store_split(g_Mh, g_Ml, (size_t)b * DP * DP, DP, acc, m0, n0, lane, wm, wn);
    } else {
        int bk = (b + 1) & (BSZ - 1);
        gemm_one(sb, mb, acc,
                 g_Yrh + ((size_t)bk * DP + m0) * HW, HW,
                 g_Ysh + ((size_t)b  * DP + n0) * HW, HW,
                 HW / 32, tid, lane, wm, wn);
        store_hi(g_Mh, (size_t)(BSZ + b) * DP * DP, DP, acc, m0, n0, lane, wm, wn);
    }
}

// ---------------- K2: T = Wq @ M'^T pos+neg, K=448 ----------------
__global__ void __launch_bounds__(256, 2)
t_kernel() {
    extern __shared__ char smem[];
    u32 sb = smem_u32(smem), mb = sb + 3*STG;
    int tid = threadIdx.x, lane = tid & 31, wid = tid >> 5, wm = wid & 1, wn = wid >> 1;
    int z = blockIdx.z, b = z >> 1, neg = z & 1;
    int m0 = blockIdx.y * 128, n0 = blockIdx.x * 128;
    float acc[4][4][4] = {};
    if (!neg) {
        gemm_main(sb, mb, acc,
                  g_Wh + (size_t)m0 * DV, g_Wl + (size_t)m0 * DV, DV,
                  g_Mh + (size_t)b * DP * DP + (size_t)n0 * DP,
                  g_Ml + (size_t)b * DP * DP + (size_t)n0 * DP, DP,
                  DV / 32, tid, lane, wm, wn);
        store_split(g_Th, g_Tl, (size_t)b * DP * DP, DP, acc, m0, n0, lane, wm, wn);
    } else {
        gemm_one(sb, mb, acc,
                 g_Wh + (size_t)m0 * DV, DV,
                 g_Mh + (size_t)(BSZ + b) * DP * DP + (size_t)n0 * DP, DP,
                 DV / 32, tid, lane, wm, wn);
        store_hi(g_Th, (size_t)(BSZ + b) * DP * DP, DP, acc, m0, n0, lane, wm, wn);
    }
}

// ---------------- K3: S = T @ Wk^T pos+neg, K=448 ----------------
__global__ void __launch_bounds__(256, 2)
s_kernel() {
    extern __shared__ char smem[];
    u32 sb = smem_u32(smem), mb = sb + 3*STG;
    int tid = threadIdx.x, lane = tid & 31, wid = tid >> 5, wm = wid & 1, wn = wid >> 1;
    int z = blockIdx.z, b = z >> 1, neg = z & 1;
    int m0 = blockIdx.y * 128, n0 = blockIdx.x * 128;
    float acc[4][4][4] = {};
    if (!neg) {
        gemm_main(sb, mb, acc,
                  g_Th + (size_t)b * DP * DP + (size_t)m0 * DP,
                  g_Tl + (size_t)b * DP * DP + (size_t)m0 * DP, DP,
                  g_Wh + ((size_t)DP + n0) * DV, g_Wl + ((size_t)DP + n0) * DV, DV,
                  DV / 32, tid, lane, wm, wn);
        store_f32(g_S + (size_t)b * DP * DP, acc, m0, n0, lane, wm, wn);
    } else {
        gemm_one(sb, mb, acc,
                 g_Th + (size_t)(BSZ + b) * DP * DP + (size_t)m0 * DP, DP,
                 g_Wh + ((size_t)DP + n0) * DV, DV,
                 DV / 32, tid, lane, wm, wn);
        store_f32(g_Sn + (size_t)b * DP * DP, acc, m0, n0, lane, wm, wn);
    }
}

// ---------------- K4: softmax; pos -> split alpha, neg -> bf16 alpha ----------------
__global__ void softmax_kernel() {
    const float inv_coef = 0.047245559126f;
    int r = blockIdx.x;
    int neg = r >= BSZ * DV, rr = neg ? r - BSZ * DV : r;
    int b = rr / DV, d = rr - b * DV;
    const float* S = (neg ? g_Sn : g_S) + ((size_t)b * DP + d) * DP;
    bf16* Oh = (neg ? g_Anhi : g_Aphi) + ((size_t)b * DP + d) * DP;
    bf16* Ol = g_Aplo + ((size_t)b * DP + d) * DP;
    int t = threadIdx.x;
    float a = S[t] * inv_coef;
    float bv = (t + 256 < DV) ? S[t + 256] * inv_coef : -1e30f;
    __shared__ float red[256];
    red[t] = fmaxf(a, bv);
    __syncthreads();
    for (int s = 128; s > 0; s >>= 1) { if (t < s) red[t] = fmaxf(red[t], red[t+s]); __syncthreads(); }
    float m = red[0];
    __syncthreads();
    float e0 = __expf(a - m), e1 = (t + 256 < DV) ? __expf(bv - m) : 0.f;
    red[t] = e0 + e1;
    __syncthreads();
    for (int s = 128; s > 0; s >>= 1) { if (t < s) red[t] += red[t+s]; __syncthreads(); }
    float inv = 1.f / red[0];
    float v0 = e0 * inv, v1 = e1 * inv;
    bf16 h0 = __float2bfloat16(v0);
    Oh[t] = h0;
    bf16 h1 = __float2bfloat16(v1);
    Oh[t + 256] = h1;                       // pad cols (>=448) stay exact 0
    if (!neg) {
        Ol[t] = __float2bfloat16(v0 - __bfloat162float(h0));
        Ol[t + 256] = __float2bfloat16(v1 - __bfloat162float(h1));
    }
}

// ---------------- K5: B2 = alpha @ Wv  pos(3-term)+neg(1-term), K=448 ----------------
__global__ void __launch_bounds__(256, 2)
b2_kernel() {
    extern __shared__ char smem[];
    u32 sb = smem_u32(smem), mb = sb + 3*STG;
    int tid = threadIdx.x, lane = tid & 31, wid = tid >> 5, wm = wid & 1, wn = wid >> 1;
    int z = blockIdx.z, b = z >> 1, neg = z & 1;
    int m0 = blockIdx.y * 128, n0 = blockIdx.x * 128;
    float acc[4][4][4] = {};
    if (!neg) {
        gemm_main(sb, mb, acc,
                  g_Aphi + ((size_t)b * DP + m0) * DP, g_Aplo + ((size_t)b * DP + m0) * DP, DP,
                  g_WvTh + (size_t)n0 * DV, g_WvTl + (size_t)n0 * DV, DV,
                  DV / 32, tid, lane, wm, wn);
        store_split(g_B2h, g_B2l, (size_t)b * DP * DP, DP, acc, m0, n0, lane, wm, wn);
    } else {
        gemm_one(sb, mb, acc,
                 g_Anhi + ((size_t)b * DP + m0) * DP, DP,
                 g_WvTh + (size_t)n0 * DV, DV,
                 DV / 32, tid, lane, wm, wn);
        store_hi(g_B2h, (size_t)(BSZ + b) * DP * DP, DP, acc, m0, n0, lane, wm, wn);
    }
}

// ---------------- K6a: out = Vs + B2p @ Vr^T (3-term, K=448) ----------------
__global__ void __launch_bounds__(256, 2)
outpos_kernel(const float* __restrict__ Vs, float* __restrict__ out) {
    extern __shared__ char smem[];
    u32 sb = smem_u32(smem), mb = sb + 3*STG;
    int tid = threadIdx.x, lane = tid & 31, wid = tid >> 5, wm = wid & 1, wn = wid >> 1;
    int b = blockIdx.z;
    int m0 = blockIdx.y * 128, n0 = blockIdx.x * 128;
    float acc[4][4][4] = {};
    gemm_main(sb, mb, acc,
              g_B2h + ((size_t)b * DP + m0) * DP, g_B2l + ((size_t)b * DP + m0) * DP, DP,
              g_Xrh + ((size_t)b * HW + n0) * DV, g_Xrl + ((size_t)b * HW + n0) * DV, DV,
              DV / 32, tid, lane, wm, wn);
#pragma unroll
    for (int mt = 0; mt < 4; mt++)
#pragma unroll
        for (int nt = 0; nt < 4; nt++)
#pragma unroll
            for (int h = 0; h < 2; h++) {
                int r = m0 + wm * 64 + mt * 16 + (lane >> 2) + h * 8;
                if (r < DV) {
                    int c = n0 + wn * 32 + nt * 8 + (lane & 3) * 2;
                    size_t g = ((size_t)b * DV + r) * HW + c;
                    float2 vs = *(const float2*)(Vs + g);
                    float2 o = {vs.x + acc[mt][nt][h*2], vs.y + acc[mt][nt][h*2+1]};
                    *(float2*)(out + g) = o;
                }
            }
}

// ---------------- K6b: v_neg = B2n @ Vr^T (1-term) ; loss vs (out - Vs) ----------------
__global__ void __launch_bounds__(256, 2)
outneg_kernel(const float* __restrict__ Vs, const float* __restrict__ out) {
    extern __shared__ char smem[];
    u32 sb = smem_u32(smem), mb = sb + 3*STG1;
    int tid = threadIdx.x, lane = tid & 31, wid = tid >> 5, wm = wid & 1, wn = wid >> 1;
    int b = blockIdx.z;
    int m0 = blockIdx.y * 128, n0 = blockIdx.x * 128;
    float acc[4][4][4] = {};
    gemm_one(sb, mb, acc,
             g_B2h + ((size_t)(BSZ + b) * DP + m0) * DP, DP,
             g_Xrh + ((size_t)b * HW + n0) * DV, DV,
             DV / 32, tid, lane, wm, wn);
    float lsum = 0.f;
#pragma unroll
    for (int mt = 0; mt < 4; mt++)
#pragma unroll
        for (int nt = 0; nt < 4; nt++)
#pragma unroll
            for (int h = 0; h < 2; h++) {
                int r = m0 + wm * 64 + mt * 16 + (lane >> 2) + h * 8;
                if (r < DV) {
                    int c = n0 + wn * 32 + nt * 8 + (lane & 3) * 2;
                    size_t g = ((size_t)b * DV + r) * HW + c;
                    float2 o = *(const float2*)(out + g);
                    float2 vs = *(const float2*)(Vs + g);
                    lsum += fmaxf(0.f, -(o.x - vs.x) + acc[mt][nt][h*2]   + 12.f)
                          + fmaxf(0.f, -(o.y - vs.y) + acc[mt][nt][h*2+1] + 12.f);
                }
            }
    __shared__ float red[256];
    red[tid] = lsum;
    __syncthreads();
    for (int s = 128; s > 0; s >>= 1) { if (tid < s) red[tid] += red[tid+s]; __syncthreads(); }
    if (tid == 0) atomicAdd(&g_Ltr, (double)red[0]);
}

__global__ void zero_kernel() { g_Ltr = 0.0; }
__global__ void final_kernel(float* out, int idx) {
    out[idx] = (float)(g_Ltr * (1.0 / ((double)BSZ * DV * HW)));
}

extern "C" void kernel_launch(void* const* d_in, const int* in_sizes, int n_in,
                              void* d_out, int out_size) {
    const float* Vr = (const float*)d_in[0];
    const float* Vs = (const float*)d_in[1];
    const float* Wq = (const float*)d_in[2];
    const float* Wk = (const float*)d_in[3];
    const float* Wv = (const float*)d_in[4];
    float* out = (float*)d_out;

    static int cfg_done = 0;
    if (!cfg_done) {
        cudaFuncSetAttribute(mm_kernel,     cudaFuncAttributeMaxDynamicSharedMemorySize, SM_GEMM);
        cudaFuncSetAttribute(t_kernel,      cudaFuncAttributeMaxDynamicSharedMemorySize, SM_GEMM);
        cudaFuncSetAttribute(s_kernel,      cudaFuncAttributeMaxDynamicSharedMemorySize, SM_GEMM);
        cudaFuncSetAttribute(b2_kernel,     cudaFuncAttributeMaxDynamicSharedMemorySize, SM_GEMM);
        cudaFuncSetAttribute(outpos_kernel, cudaFuncAttributeMaxDynamicSharedMemorySize, SM_GEMM);
        cudaFuncSetAttribute(outneg_kernel, cudaFuncAttributeMaxDynamicSharedMemorySize, SM_GEMM);
        cfg_done = 1;
    }

    zero_kernel<<<1, 1>>>();
    convw_kernel<<<(3 * DV * DV / 2 + 255) / 256, 256>>>(Wq, Wk, Wv);
    convy_kernel<<<dim3(HW / 512, DV, BSZ * 2), 256>>>(Vr, Vs);
    convx_kernel<<<dim3(HW / 32, DV / 32, BSZ), 256>>>(Vr);
    mm_kernel<<<dim3(DP/128, DP/128, BSZ*2), 256, SM_GEMM>>>();
    t_kernel <<<dim3(DP/128, DP/128, BSZ*2), 256, SM_GEMM>>>();
    s_kernel <<<dim3(DP/128, DP/128, BSZ*2), 256, SM_GEMM>>>();
    softmax_kernel<<<2 * BSZ * DV, 256>>>();
    b2_kernel<<<dim3(DP/128, DP/128, BSZ*2), 256, SM_GEMM>>>();
    outpos_kernel<<<dim3(HW/128, DP/128, BSZ), 256, SM_GEMM>>>(Vs, out);
    outneg_kernel<<<dim3(HW/128, DP/128, BSZ), 256, SM_GEMM>>>(Vs, out);
    final_kernel<<<1, 1>>>(out, out_size - 1);
}